// round 3
// baseline (speedup 1.0000x reference)
#include <cuda_runtime.h>

#define BB   1024
#define AA   64
#define NN   256
#define MM   128
#define HH   64
#define EATT 64
#define ACTD 64
#define KK   8
#define ROWS (BB*AA)

// ---- scratch (device globals; no allocations allowed) ----
__device__ float g_thoughts[ROWS * MM];   // 32 MB
__device__ float g_newt[ROWS * MM];       // 32 MB
__device__ int   g_gidx[ROWS * KK];       // 2 MB
__device__ int   g_isinit[ROWS];          // 256 KB

// =====================================================================
// K1: actor_1  obs -> Linear(256,128) -> LayerNorm -> ReLU -> Linear(128,128)
// 4 rows per CTA, 128 threads per row (one output per thread).
// =====================================================================
__global__ __launch_bounds__(512) void k1_actor1(
    const float* __restrict__ obs,
    const float* __restrict__ w1, const float* __restrict__ b1,
    const float* __restrict__ lng, const float* __restrict__ lnb,
    const float* __restrict__ w2, const float* __restrict__ b2)
{
    __shared__ float obs_sm[4][NN];
    __shared__ float h_sm[4][MM];
    __shared__ float redA[4][4];
    __shared__ float redB[4][4];

    int tx = threadIdx.x;
    int rl = tx >> 7;        // row-in-CTA 0..3
    int o  = tx & 127;       // output index
    long rowbase = (long)blockIdx.x * 4;

    const float* obsg = obs + rowbase * NN;
    for (int i = tx; i < 4 * NN; i += 512) obs_sm[i >> 8][i & 255] = obsg[i];
    __syncthreads();

    // h = W1 @ obs + b1
    float acc = b1[o];
    const float4* wr = (const float4*)(w1 + o * NN);
    #pragma unroll 8
    for (int j = 0; j < NN / 4; j++) {
        float4 w = wr[j];
        float4 x = *(const float4*)&obs_sm[rl][j * 4];
        acc += w.x * x.x + w.y * x.y + w.z * x.z + w.w * x.w;
    }

    // layernorm (two-pass for accuracy)
    float s = acc;
    for (int off = 16; off; off >>= 1) s += __shfl_down_sync(0xffffffffu, s, off);
    int wir = o >> 5;
    if ((o & 31) == 0) redA[rl][wir] = s;
    __syncthreads();
    float mu = (redA[rl][0] + redA[rl][1] + redA[rl][2] + redA[rl][3]) * (1.0f / MM);
    float d  = acc - mu;
    float s2 = d * d;
    for (int off = 16; off; off >>= 1) s2 += __shfl_down_sync(0xffffffffu, s2, off);
    if ((o & 31) == 0) redB[rl][wir] = s2;
    __syncthreads();
    float var = (redB[rl][0] + redB[rl][1] + redB[rl][2] + redB[rl][3]) * (1.0f / MM);
    float v = d * rsqrtf(var + 1e-5f) * lng[o] + lnb[o];
    h_sm[rl][o] = fmaxf(v, 0.0f);
    __syncthreads();

    // thoughts = W2 @ relu(h) + b2
    float acc2 = b2[o];
    const float4* wr2 = (const float4*)(w2 + o * MM);
    #pragma unroll 8
    for (int j = 0; j < MM / 4; j++) {
        float4 w = wr2[j];
        float4 x = *(const float4*)&h_sm[rl][j * 4];
        acc2 += w.x * x.x + w.y * x.y + w.z * x.z + w.w * x.w;
    }
    g_thoughts[(rowbase + rl) * MM + o] = acc2;
}

// =====================================================================
// K2: attention MLP -> is_init flag.  sigmoid(logit)>0.5  <=>  logit>0
// 4 rows per CTA, 64 threads per row.
// =====================================================================
__global__ __launch_bounds__(256) void k2_att(
    const float* __restrict__ w1, const float* __restrict__ b1,
    const float* __restrict__ w2, const float* __restrict__ b2,
    const float* __restrict__ w3, const float* __restrict__ b3)
{
    __shared__ float t_sm[4][MM];
    __shared__ float a_sm[4][EATT];
    __shared__ float c_sm[4][EATT];
    __shared__ float red[4][2];

    int tx = threadIdx.x;
    int rl = tx >> 6;
    int u  = tx & 63;
    long rowbase = (long)blockIdx.x * 4;

    const float* tg = g_thoughts + rowbase * MM;
    for (int i = tx; i < 4 * MM; i += 256) t_sm[i >> 7][i & 127] = tg[i];
    __syncthreads();

    float acc = b1[u];
    const float4* wr = (const float4*)(w1 + u * MM);
    #pragma unroll
    for (int j = 0; j < MM / 4; j++) {
        float4 w = wr[j];
        float4 x = *(const float4*)&t_sm[rl][j * 4];
        acc += w.x * x.x + w.y * x.y + w.z * x.z + w.w * x.w;
    }
    a_sm[rl][u] = fmaxf(acc, 0.0f);
    __syncthreads();

    float acc2 = b2[u];
    const float4* wr2 = (const float4*)(w2 + u * EATT);
    #pragma unroll
    for (int j = 0; j < EATT / 4; j++) {
        float4 w = wr2[j];
        float4 x = *(const float4*)&a_sm[rl][j * 4];
        acc2 += w.x * x.x + w.y * x.y + w.z * x.z + w.w * x.w;
    }
    c_sm[rl][u] = fmaxf(acc2, 0.0f);
    __syncthreads();

    float p = w3[u] * c_sm[rl][u];
    for (int off = 16; off; off >>= 1) p += __shfl_down_sync(0xffffffffu, p, off);
    if ((u & 31) == 0) red[rl][u >> 5] = p;
    __syncthreads();
    if (u == 0) {
        float logit = red[rl][0] + red[rl][1] + b3[0];
        g_isinit[rowbase + rl] = (logit > 0.0f) ? 1 : 0;
    }
}

// =====================================================================
// K3: pairwise squared distances (A x A per batch) + stable top-8 by
// (dist, index), output indices sorted ascending.  One CTA per batch.
// =====================================================================
#define TP 132  // padded row stride (words): keeps float4 alignment, breaks conflicts
__global__ __launch_bounds__(256) void k3_groups()
{
    __shared__ float th[AA][TP];
    __shared__ float sq[AA];

    int tx = threadIdx.x;
    int b  = blockIdx.x;
    const float* tg = g_thoughts + (long)b * AA * MM;
    for (int i = tx; i < AA * MM; i += 256) th[i >> 7][i & 127] = tg[i];
    __syncthreads();

    if (tx < AA) {
        float s = 0.0f;
        #pragma unroll 16
        for (int c = 0; c < MM; c++) { float v = th[tx][c]; s += v * v; }
        sq[tx] = s;
    }
    __syncthreads();

    int warp = tx >> 5, lane = tx & 31;
    for (int i = warp; i < AA; i += 8) {
        int j0 = lane, j1 = lane + 32;
        float d0 = 0.0f, d1 = 0.0f;
        #pragma unroll 8
        for (int c = 0; c < MM; c += 4) {
            float4 xi = *(const float4*)&th[i][c];
            float4 xa = *(const float4*)&th[j0][c];
            float4 xb = *(const float4*)&th[j1][c];
            d0 += xi.x * xa.x + xi.y * xa.y + xi.z * xa.z + xi.w * xa.w;
            d1 += xi.x * xb.x + xi.y * xb.y + xi.z * xb.z + xi.w * xb.w;
        }
        d0 = sq[i] + sq[j0] - 2.0f * d0;
        d1 = sq[i] + sq[j1] - 2.0f * d1;

        int sel[KK];
        #pragma unroll
        for (int t = 0; t < KK; t++) {
            float md; int mj;
            if (d0 <= d1) { md = d0; mj = j0; } else { md = d1; mj = j1; }
            for (int off = 16; off; off >>= 1) {
                float od = __shfl_down_sync(0xffffffffu, md, off);
                int   oj = __shfl_down_sync(0xffffffffu, mj, off);
                if (od < md || (od == md && oj < mj)) { md = od; mj = oj; }
            }
            mj = __shfl_sync(0xffffffffu, mj, 0);
            sel[t] = mj;
            if (mj == j0) d0 = 3.4e38f;
            if (mj == j1) d1 = 3.4e38f;
        }
        // sort chosen indices ascending (matches reference's final sort)
        #pragma unroll
        for (int p = 0; p < KK; p++)
            #pragma unroll
            for (int q = 0; q < KK - 1; q++)
                if (sel[q] > sel[q + 1]) { int t2 = sel[q]; sel[q] = sel[q + 1]; sel[q + 1] = t2; }
        if (lane < KK) g_gidx[((long)b * AA + i) * KK + lane] = sel[lane];
    }
}

// =====================================================================
// K4: sequential gather -> bi-LSTM -> scatter per initiator, in agent
// order, with state resident in SMEM.  One CTA per batch, 512 threads:
// t<256: forward gate t; t>=256: backward gate t-256.
// Whh row lives in registers; Wih streamed from L2 (shared by all CTAs).
// =====================================================================
__device__ __forceinline__ float sigm(float x) { return 1.0f / (1.0f + __expf(-x)); }

__global__ __launch_bounds__(512, 1) void k4_lstm(
    const float* __restrict__ wih_f, const float* __restrict__ whh_f,
    const float* __restrict__ bih_f, const float* __restrict__ bhh_f,
    const float* __restrict__ wih_b, const float* __restrict__ whh_b,
    const float* __restrict__ bih_b, const float* __restrict__ bhh_b)
{
    __shared__ float nt[AA * MM];       // current thought state (32 KB)
    __shared__ float z_sm[512];
    __shared__ float h_sm[2 * HH];
    __shared__ float hist[2][KK][HH];   // [dir][timestep][unit]
    __shared__ int   idx_sm[KK];

    int tx  = threadIdx.x;
    int b   = blockIdx.x;
    int dir = tx >> 8;
    int g   = tx & 255;

    const float* wih = dir ? wih_b : wih_f;
    const float* whh = dir ? whh_b : whh_f;
    float bsum = dir ? (bih_b[g] + bhh_b[g]) : (bih_f[g] + bhh_f[g]);

    float wr[HH];                       // Whh row, register-resident
    #pragma unroll
    for (int j = 0; j < HH; j++) wr[j] = whh[g * HH + j];

    const float* tg = g_thoughts + (long)b * AA * MM;
    for (int i = tx; i < AA * MM; i += 512) nt[i] = tg[i];

    const int* idxg  = g_gidx   + (long)b * AA * KK;
    const int* initg = g_isinit + (long)b * AA;
    bool is_gate = (g < HH);
    __syncthreads();

    for (int a = 0; a < AA; a++) {
        if (!initg[a]) continue;        // uniform across block

        if (tx < KK) idx_sm[tx] = idxg[a * KK + tx];
        float cst = 0.0f;
        if (is_gate) h_sm[dir * HH + g] = 0.0f;
        __syncthreads();

        int id[KK];
        #pragma unroll
        for (int k = 0; k < KK; k++) id[k] = idx_sm[k] * MM;

        // input projections for all 8 timesteps (hoisted out of recurrence)
        float xz[KK];
        #pragma unroll
        for (int k = 0; k < KK; k++) xz[k] = bsum;
        const float* wrow = wih + g * MM;
        #pragma unroll 4
        for (int jc = 0; jc < MM; jc += 4) {
            float4 w = *(const float4*)(wrow + jc);
            #pragma unroll
            for (int k = 0; k < KK; k++) {
                float4 x = *(const float4*)&nt[id[k] + jc];
                xz[k] += w.x * x.x + w.y * x.y + w.z * x.z + w.w * x.w;
            }
        }

        // recurrence (fwd consumes k=s, bwd consumes k=7-s)
        const float* hp = &h_sm[dir * HH];
        for (int s = 0; s < KK; s++) {
            int ks = dir ? (KK - 1 - s) : s;
            float z = xz[ks];
            #pragma unroll
            for (int j = 0; j < HH; j += 4) {
                float4 h4 = *(const float4*)&hp[j];
                z += wr[j] * h4.x + wr[j + 1] * h4.y + wr[j + 2] * h4.z + wr[j + 3] * h4.w;
            }
            z_sm[tx] = z;
            __syncthreads();
            if (is_gate) {
                int base = dir * 256;
                float zi = z_sm[base + g];
                float zf = z_sm[base + 64 + g];
                float zg = z_sm[base + 128 + g];
                float zo = z_sm[base + 192 + g];
                cst = sigm(zf) * cst + sigm(zi) * tanhf(zg);
                float h = sigm(zo) * tanhf(cst);
                h_sm[dir * HH + g] = h;
                hist[dir][ks][g] = h;
            }
            __syncthreads();
        }

        // scatter: nt[idx[k]] = [h_fwd(k) ; h_bwd(k)]
        for (int e = tx; e < KK * MM; e += 512) {
            int k = e >> 7, c = e & 127;
            float v = (c < HH) ? hist[0][k][c] : hist[1][k][c - HH];
            nt[idx_sm[k] * MM + c] = v;
        }
        __syncthreads();
    }

    float* og = g_newt + (long)b * AA * MM;
    for (int i = tx; i < AA * MM; i += 512) og[i] = nt[i];
}

// =====================================================================
// K5: actor_2  relu(concat) -> Linear(256,128)+b -> Linear(128,64) -> tanh
// =====================================================================
__global__ __launch_bounds__(512) void k5_actor2(
    const float* __restrict__ w1, const float* __restrict__ b1,
    const float* __restrict__ w2, float* __restrict__ out)
{
    __shared__ float x_sm[4][2 * MM];
    __shared__ float e_sm[4][MM];

    int tx = threadIdx.x;
    int rl = tx >> 7;
    int o  = tx & 127;
    long rowbase = (long)blockIdx.x * 4;

    for (int i = tx; i < 4 * 2 * MM; i += 512) {
        int r = i >> 8, c = i & 255;
        float v = (c < MM) ? g_thoughts[(rowbase + r) * MM + c]
                           : g_newt[(rowbase + r) * MM + (c - MM)];
        x_sm[r][c] = fmaxf(v, 0.0f);
    }
    __syncthreads();

    float acc = b1[o];
    const float4* wr = (const float4*)(w1 + o * 2 * MM);
    #pragma unroll 8
    for (int j = 0; j < 2 * MM / 4; j++) {
        float4 w = wr[j];
        float4 x = *(const float4*)&x_sm[rl][j * 4];
        acc += w.x * x.x + w.y * x.y + w.z * x.z + w.w * x.w;
    }
    e_sm[rl][o] = acc;
    __syncthreads();

    if (o < ACTD) {
        float a2 = 0.0f;
        const float4* wr2 = (const float4*)(w2 + o * MM);
        #pragma unroll 8
        for (int j = 0; j < MM / 4; j++) {
            float4 w = wr2[j];
            float4 x = *(const float4*)&e_sm[rl][j * 4];
            a2 += w.x * x.x + w.y * x.y + w.z * x.z + w.w * x.w;
        }
        out[(rowbase + rl) * ACTD + o] = tanhf(a2);
    }
}

// =====================================================================
extern "C" void kernel_launch(void* const* d_in, const int* in_sizes, int n_in,
                              void* d_out, int out_size)
{
    const float* obs    = (const float*)d_in[0];
    const float* a1_w1  = (const float*)d_in[1];
    const float* a1_b1  = (const float*)d_in[2];
    const float* ln_g   = (const float*)d_in[3];
    const float* ln_b   = (const float*)d_in[4];
    const float* a1_w2  = (const float*)d_in[5];
    const float* a1_b2  = (const float*)d_in[6];
    const float* att_w1 = (const float*)d_in[7];
    const float* att_b1 = (const float*)d_in[8];
    const float* att_w2 = (const float*)d_in[9];
    const float* att_b2 = (const float*)d_in[10];
    const float* att_w3 = (const float*)d_in[11];
    const float* att_b3 = (const float*)d_in[12];
    const float* wih_f  = (const float*)d_in[13];
    const float* whh_f  = (const float*)d_in[14];
    const float* bih_f  = (const float*)d_in[15];
    const float* bhh_f  = (const float*)d_in[16];
    const float* wih_b  = (const float*)d_in[17];
    const float* whh_b  = (const float*)d_in[18];
    const float* bih_b  = (const float*)d_in[19];
    const float* bhh_b  = (const float*)d_in[20];
    const float* a2_w1  = (const float*)d_in[21];
    const float* a2_b1  = (const float*)d_in[22];
    const float* a2_w2  = (const float*)d_in[23];
    float* out = (float*)d_out;

    k1_actor1<<<ROWS / 4, 512>>>(obs, a1_w1, a1_b1, ln_g, ln_b, a1_w2, a1_b2);
    k2_att<<<ROWS / 4, 256>>>(att_w1, att_b1, att_w2, att_b2, att_w3, att_b3);
    k3_groups<<<BB, 256>>>();
    k4_lstm<<<BB, 512>>>(wih_f, whh_f, bih_f, bhh_f, wih_b, whh_b, bih_b, bhh_b);
    k5_actor2<<<ROWS / 4, 512>>>(a2_w1, a2_b1, a2_w2, out);
}

// round 4
// speedup vs baseline: 1.0610x; 1.0610x over previous
#include <cuda_runtime.h>

#define BB   1024
#define AA   64
#define NN   256
#define MM   128
#define HH   64
#define EATT 64
#define ACTD 64
#define KK   8
#define ROWS (BB*AA)
#define WPAD 132   // padded weight-row stride in floats (conflict-free for LDS.128 8-lane phases)

// ---- scratch (device globals; no allocations allowed) ----
__device__ float g_thoughts[ROWS * MM];   // 32 MB
__device__ float g_newt[ROWS * MM];       // 32 MB
__device__ int   g_gidx[ROWS * KK];       // 2 MB
__device__ int   g_isinit[ROWS];          // 256 KB

// ---- packed fp32x2 FMA helpers (Blackwell FFMA2) ----
__device__ __forceinline__ unsigned long long fma2(unsigned long long a,
                                                   unsigned long long b,
                                                   unsigned long long c)
{
    unsigned long long d;
    asm("fma.rn.f32x2 %0, %1, %2, %3;" : "=l"(d) : "l"(a), "l"(b), "l"(c));
    return d;
}
__device__ __forceinline__ float lohi(unsigned long long v)
{
    float lo = __uint_as_float((unsigned)(v & 0xffffffffull));
    float hi = __uint_as_float((unsigned)(v >> 32));
    return lo + hi;
}

// =====================================================================
// K1: actor_1  obs -> Linear(256,128) -> LayerNorm -> ReLU -> Linear(128,128)
// 4 rows per CTA, 128 threads per row (one output per thread).
// =====================================================================
__global__ __launch_bounds__(512) void k1_actor1(
    const float* __restrict__ obs,
    const float* __restrict__ w1, const float* __restrict__ b1,
    const float* __restrict__ lng, const float* __restrict__ lnb,
    const float* __restrict__ w2, const float* __restrict__ b2)
{
    __shared__ __align__(16) float obs_sm[4][NN];
    __shared__ __align__(16) float h_sm[4][MM];
    __shared__ float redA[4][4];
    __shared__ float redB[4][4];

    int tx = threadIdx.x;
    int rl = tx >> 7;        // row-in-CTA 0..3
    int o  = tx & 127;       // output index
    long rowbase = (long)blockIdx.x * 4;

    const float* obsg = obs + rowbase * NN;
    for (int i = tx; i < 4 * NN; i += 512) obs_sm[i >> 8][i & 255] = obsg[i];
    __syncthreads();

    // h = W1 @ obs + b1   (packed f32x2)
    unsigned long long a0 = 0ull, a1 = 0ull;
    const float* wr = w1 + o * NN;
    #pragma unroll 8
    for (int j = 0; j < NN; j += 4) {
        longlong2 w = *(const longlong2*)(wr + j);
        longlong2 x = *(const longlong2*)&obs_sm[rl][j];
        a0 = fma2(w.x, x.x, a0);
        a1 = fma2(w.y, x.y, a1);
    }
    float acc = b1[o] + lohi(a0) + lohi(a1);

    // layernorm (two-pass for accuracy)
    float s = acc;
    for (int off = 16; off; off >>= 1) s += __shfl_down_sync(0xffffffffu, s, off);
    int wir = o >> 5;
    if ((o & 31) == 0) redA[rl][wir] = s;
    __syncthreads();
    float mu = (redA[rl][0] + redA[rl][1] + redA[rl][2] + redA[rl][3]) * (1.0f / MM);
    float d  = acc - mu;
    float s2 = d * d;
    for (int off = 16; off; off >>= 1) s2 += __shfl_down_sync(0xffffffffu, s2, off);
    if ((o & 31) == 0) redB[rl][wir] = s2;
    __syncthreads();
    float var = (redB[rl][0] + redB[rl][1] + redB[rl][2] + redB[rl][3]) * (1.0f / MM);
    float v = d * rsqrtf(var + 1e-5f) * lng[o] + lnb[o];
    h_sm[rl][o] = fmaxf(v, 0.0f);
    __syncthreads();

    // thoughts = W2 @ relu(h) + b2
    unsigned long long c0 = 0ull, c1 = 0ull;
    const float* wr2 = w2 + o * MM;
    #pragma unroll 8
    for (int j = 0; j < MM; j += 4) {
        longlong2 w = *(const longlong2*)(wr2 + j);
        longlong2 x = *(const longlong2*)&h_sm[rl][j];
        c0 = fma2(w.x, x.x, c0);
        c1 = fma2(w.y, x.y, c1);
    }
    g_thoughts[(rowbase + rl) * MM + o] = b2[o] + lohi(c0) + lohi(c1);
}

// =====================================================================
// K2: attention MLP -> is_init flag.  sigmoid(logit)>0.5  <=>  logit>0
// =====================================================================
__global__ __launch_bounds__(256) void k2_att(
    const float* __restrict__ w1, const float* __restrict__ b1,
    const float* __restrict__ w2, const float* __restrict__ b2,
    const float* __restrict__ w3, const float* __restrict__ b3)
{
    __shared__ __align__(16) float t_sm[4][MM];
    __shared__ __align__(16) float a_sm[4][EATT];
    __shared__ __align__(16) float c_sm[4][EATT];
    __shared__ float red[4][2];

    int tx = threadIdx.x;
    int rl = tx >> 6;
    int u  = tx & 63;
    long rowbase = (long)blockIdx.x * 4;

    const float* tg = g_thoughts + rowbase * MM;
    for (int i = tx; i < 4 * MM; i += 256) t_sm[i >> 7][i & 127] = tg[i];
    __syncthreads();

    unsigned long long a0 = 0ull, a1 = 0ull;
    const float* wr = w1 + u * MM;
    #pragma unroll 8
    for (int j = 0; j < MM; j += 4) {
        longlong2 w = *(const longlong2*)(wr + j);
        longlong2 x = *(const longlong2*)&t_sm[rl][j];
        a0 = fma2(w.x, x.x, a0);
        a1 = fma2(w.y, x.y, a1);
    }
    a_sm[rl][u] = fmaxf(b1[u] + lohi(a0) + lohi(a1), 0.0f);
    __syncthreads();

    unsigned long long c0 = 0ull, c1 = 0ull;
    const float* wr2 = w2 + u * EATT;
    #pragma unroll 8
    for (int j = 0; j < EATT; j += 4) {
        longlong2 w = *(const longlong2*)(wr2 + j);
        longlong2 x = *(const longlong2*)&a_sm[rl][j];
        c0 = fma2(w.x, x.x, c0);
        c1 = fma2(w.y, x.y, c1);
    }
    c_sm[rl][u] = fmaxf(b2[u] + lohi(c0) + lohi(c1), 0.0f);
    __syncthreads();

    float p = w3[u] * c_sm[rl][u];
    for (int off = 16; off; off >>= 1) p += __shfl_down_sync(0xffffffffu, p, off);
    if ((u & 31) == 0) red[rl][u >> 5] = p;
    __syncthreads();
    if (u == 0) {
        float logit = red[rl][0] + red[rl][1] + b3[0];
        g_isinit[rowbase + rl] = (logit > 0.0f) ? 1 : 0;
    }
}

// =====================================================================
// K3: pairwise squared distances + stable top-8 by (dist, index),
// output indices sorted ascending.  One CTA per batch.
// =====================================================================
#define TP 132
__global__ __launch_bounds__(256) void k3_groups()
{
    __shared__ __align__(16) float th[AA][TP];
    __shared__ float sq[AA];

    int tx = threadIdx.x;
    int b  = blockIdx.x;
    const float* tg = g_thoughts + (long)b * AA * MM;
    for (int i = tx; i < AA * MM; i += 256) th[i >> 7][i & 127] = tg[i];
    __syncthreads();

    if (tx < AA) {
        float s = 0.0f;
        #pragma unroll 16
        for (int c = 0; c < MM; c++) { float v = th[tx][c]; s += v * v; }
        sq[tx] = s;
    }
    __syncthreads();

    int warp = tx >> 5, lane = tx & 31;
    for (int i = warp; i < AA; i += 8) {
        int j0 = lane, j1 = lane + 32;
        float d0 = 0.0f, d1 = 0.0f;
        #pragma unroll 8
        for (int c = 0; c < MM; c += 4) {
            float4 xi = *(const float4*)&th[i][c];
            float4 xa = *(const float4*)&th[j0][c];
            float4 xb = *(const float4*)&th[j1][c];
            d0 += xi.x * xa.x + xi.y * xa.y + xi.z * xa.z + xi.w * xa.w;
            d1 += xi.x * xb.x + xi.y * xb.y + xi.z * xb.z + xi.w * xb.w;
        }
        d0 = sq[i] + sq[j0] - 2.0f * d0;
        d1 = sq[i] + sq[j1] - 2.0f * d1;

        int sel[KK];
        #pragma unroll
        for (int t = 0; t < KK; t++) {
            float md; int mj;
            if (d0 <= d1) { md = d0; mj = j0; } else { md = d1; mj = j1; }
            for (int off = 16; off; off >>= 1) {
                float od = __shfl_down_sync(0xffffffffu, md, off);
                int   oj = __shfl_down_sync(0xffffffffu, mj, off);
                if (od < md || (od == md && oj < mj)) { md = od; mj = oj; }
            }
            mj = __shfl_sync(0xffffffffu, mj, 0);
            sel[t] = mj;
            if (mj == j0) d0 = 3.4e38f;
            if (mj == j1) d1 = 3.4e38f;
        }
        #pragma unroll
        for (int p = 0; p < KK; p++)
            #pragma unroll
            for (int q = 0; q < KK - 1; q++)
                if (sel[q] > sel[q + 1]) { int t2 = sel[q]; sel[q] = sel[q + 1]; sel[q + 1] = t2; }
        if (lane < KK) g_gidx[((long)b * AA + i) * KK + lane] = sel[lane];
    }
}

// =====================================================================
// K4: sequential gather -> bi-LSTM -> scatter per initiator.
// One CTA per batch, 512 threads (warps 0-7: fwd gates, 8-15: bwd gates).
// Wih_fwd lives in SMEM (no L1 thrash); Wih_bwd streams from L2/L1.
// Whh row lives in registers as packed f32x2 pairs.  All inner products
// use fma.rn.f32x2.
// =====================================================================
__device__ __forceinline__ float sigm(float x) { return 1.0f / (1.0f + __expf(-x)); }

__global__ __launch_bounds__(512, 1) void k4_lstm(
    const float* __restrict__ wih_f, const float* __restrict__ whh_f,
    const float* __restrict__ bih_f, const float* __restrict__ bhh_f,
    const float* __restrict__ wih_b, const float* __restrict__ whh_b,
    const float* __restrict__ bih_b, const float* __restrict__ bhh_b)
{
    extern __shared__ __align__(16) float dynsm[];
    float* nt   = dynsm;            // AA*MM = 8192 floats (32 KB)
    float* w_sm = dynsm + AA * MM;  // 256 rows x WPAD floats (135 KB), Wih_fwd

    __shared__ __align__(16) float z_sm[512];
    __shared__ __align__(16) float h_sm[2 * HH];
    __shared__ __align__(16) float hist[2][KK][HH];
    __shared__ int   idx_sm[KK];

    int tx  = threadIdx.x;
    int b   = blockIdx.x;
    int dir = tx >> 8;          // warp-aligned: warps 0-7 fwd, 8-15 bwd
    int g   = tx & 255;

    const float* whh = dir ? whh_b : whh_f;
    float bsum = dir ? (bih_b[g] + bhh_b[g]) : (bih_f[g] + bhh_f[g]);

    // Whh row, register-resident as 32 packed f32x2 pairs (64 regs)
    unsigned long long wr2[HH / 2];
    {
        const float* w = whh + g * HH;
        #pragma unroll
        for (int j = 0; j < HH; j += 4) {
            longlong2 t = *(const longlong2*)(w + j);
            wr2[(j >> 1)]     = t.x;
            wr2[(j >> 1) + 1] = t.y;
        }
    }

    // stage Wih_fwd into smem (padded stride)
    for (int i = tx; i < 256 * MM; i += 512) {
        int r = i >> 7, c = i & 127;
        w_sm[r * WPAD + c] = wih_f[i];
    }
    // load thought state
    const float* tg = g_thoughts + (long)b * AA * MM;
    for (int i = tx; i < AA * MM; i += 512) nt[i] = tg[i];

    const float* wrow = dir ? (wih_b + g * MM) : (w_sm + g * WPAD);

    const int* idxg  = g_gidx   + (long)b * AA * KK;
    const int* initg = g_isinit + (long)b * AA;
    bool is_gate = (g < HH);
    __syncthreads();

    for (int a = 0; a < AA; a++) {
        if (!initg[a]) continue;        // uniform across block

        if (tx < KK) idx_sm[tx] = idxg[a * KK + tx];
        float cst = 0.0f;
        if (is_gate) h_sm[dir * HH + g] = 0.0f;
        __syncthreads();

        int id[KK];
        #pragma unroll
        for (int k = 0; k < KK; k++) id[k] = idx_sm[k] * MM;

        // input projections for all 8 timesteps (hoisted), packed f32x2
        unsigned long long acc[KK];
        #pragma unroll
        for (int k = 0; k < KK; k++) acc[k] = 0ull;
        #pragma unroll 4
        for (int jc = 0; jc < MM; jc += 4) {
            longlong2 w2 = *(const longlong2*)(wrow + jc);
            #pragma unroll
            for (int k = 0; k < KK; k++) {
                longlong2 x2 = *(const longlong2*)(nt + id[k] + jc);
                acc[k] = fma2(w2.x, x2.x, acc[k]);
                acc[k] = fma2(w2.y, x2.y, acc[k]);
            }
        }
        float xz[KK];
        #pragma unroll
        for (int k = 0; k < KK; k++) xz[k] = bsum + lohi(acc[k]);

        // recurrence (fwd consumes k=s, bwd consumes k=7-s)
        const float* hp = &h_sm[dir * HH];
        for (int s = 0; s < KK; s++) {
            int ks = dir ? (KK - 1 - s) : s;
            unsigned long long r0 = 0ull, r1 = 0ull;
            #pragma unroll
            for (int j = 0; j < HH; j += 4) {
                longlong2 h2 = *(const longlong2*)(hp + j);
                r0 = fma2(wr2[(j >> 1)],     h2.x, r0);
                r1 = fma2(wr2[(j >> 1) + 1], h2.y, r1);
            }
            z_sm[tx] = xz[ks] + lohi(r0) + lohi(r1);
            __syncthreads();
            if (is_gate) {
                int base = dir * 256;
                float zi = z_sm[base + g];
                float zf = z_sm[base + 64 + g];
                float zg = z_sm[base + 128 + g];
                float zo = z_sm[base + 192 + g];
                cst = sigm(zf) * cst + sigm(zi) * tanhf(zg);
                float h = sigm(zo) * tanhf(cst);
                h_sm[dir * HH + g] = h;
                hist[dir][ks][g] = h;
            }
            __syncthreads();
        }

        // scatter: nt[idx[k]] = [h_fwd(k) ; h_bwd(k)]
        for (int e = tx; e < KK * MM; e += 512) {
            int k = e >> 7, c = e & 127;
            float v = (c < HH) ? hist[0][k][c] : hist[1][k][c - HH];
            nt[idx_sm[k] * MM + c] = v;
        }
        __syncthreads();
    }

    float* og = g_newt + (long)b * AA * MM;
    for (int i = tx; i < AA * MM; i += 512) og[i] = nt[i];
}

// =====================================================================
// K5: actor_2  relu(concat) -> Linear(256,128)+b -> Linear(128,64) -> tanh
// =====================================================================
__global__ __launch_bounds__(512) void k5_actor2(
    const float* __restrict__ w1, const float* __restrict__ b1,
    const float* __restrict__ w2, float* __restrict__ out)
{
    __shared__ __align__(16) float x_sm[4][2 * MM];
    __shared__ __align__(16) float e_sm[4][MM];

    int tx = threadIdx.x;
    int rl = tx >> 7;
    int o  = tx & 127;
    long rowbase = (long)blockIdx.x * 4;

    for (int i = tx; i < 4 * 2 * MM; i += 512) {
        int r = i >> 8, c = i & 255;
        float v = (c < MM) ? g_thoughts[(rowbase + r) * MM + c]
                           : g_newt[(rowbase + r) * MM + (c - MM)];
        x_sm[r][c] = fmaxf(v, 0.0f);
    }
    __syncthreads();

    unsigned long long a0 = 0ull, a1 = 0ull;
    const float* wr = w1 + o * 2 * MM;
    #pragma unroll 8
    for (int j = 0; j < 2 * MM; j += 4) {
        longlong2 w = *(const longlong2*)(wr + j);
        longlong2 x = *(const longlong2*)&x_sm[rl][j];
        a0 = fma2(w.x, x.x, a0);
        a1 = fma2(w.y, x.y, a1);
    }
    e_sm[rl][o] = b1[o] + lohi(a0) + lohi(a1);
    __syncthreads();

    if (o < ACTD) {
        unsigned long long c0 = 0ull, c1 = 0ull;
        const float* wr2 = w2 + o * MM;
        #pragma unroll 8
        for (int j = 0; j < MM; j += 4) {
            longlong2 w = *(const longlong2*)(wr2 + j);
            longlong2 x = *(const longlong2*)&e_sm[rl][j];
            c0 = fma2(w.x, x.x, c0);
            c1 = fma2(w.y, x.y, c1);
        }
        out[(rowbase + rl) * ACTD + o] = tanhf(lohi(c0) + lohi(c1));
    }
}

// =====================================================================
extern "C" void kernel_launch(void* const* d_in, const int* in_sizes, int n_in,
                              void* d_out, int out_size)
{
    const float* obs    = (const float*)d_in[0];
    const float* a1_w1  = (const float*)d_in[1];
    const float* a1_b1  = (const float*)d_in[2];
    const float* ln_g   = (const float*)d_in[3];
    const float* ln_b   = (const float*)d_in[4];
    const float* a1_w2  = (const float*)d_in[5];
    const float* a1_b2  = (const float*)d_in[6];
    const float* att_w1 = (const float*)d_in[7];
    const float* att_b1 = (const float*)d_in[8];
    const float* att_w2 = (const float*)d_in[9];
    const float* att_b2 = (const float*)d_in[10];
    const float* att_w3 = (const float*)d_in[11];
    const float* att_b3 = (const float*)d_in[12];
    const float* wih_f  = (const float*)d_in[13];
    const float* whh_f  = (const float*)d_in[14];
    const float* bih_f  = (const float*)d_in[15];
    const float* bhh_f  = (const float*)d_in[16];
    const float* wih_b  = (const float*)d_in[17];
    const float* whh_b  = (const float*)d_in[18];
    const float* bih_b  = (const float*)d_in[19];
    const float* bhh_b  = (const float*)d_in[20];
    const float* a2_w1  = (const float*)d_in[21];
    const float* a2_b1  = (const float*)d_in[22];
    const float* a2_w2  = (const float*)d_in[23];
    float* out = (float*)d_out;

    // dynamic smem for k4: nt (32 KB) + padded Wih_fwd (135 KB)
    const int k4_smem = (AA * MM + 256 * WPAD) * (int)sizeof(float);
    static int attr_done = 0;
    if (!attr_done) {
        cudaFuncSetAttribute(k4_lstm, cudaFuncAttributeMaxDynamicSharedMemorySize, k4_smem);
        attr_done = 1;
    }

    k1_actor1<<<ROWS / 4, 512>>>(obs, a1_w1, a1_b1, ln_g, ln_b, a1_w2, a1_b2);
    k2_att<<<ROWS / 4, 256>>>(att_w1, att_b1, att_w2, att_b2, att_w3, att_b3);
    k3_groups<<<BB, 256>>>();
    k4_lstm<<<BB, 512, k4_smem>>>(wih_f, whh_f, bih_f, bhh_f, wih_b, whh_b, bih_b, bhh_b);
    k5_actor2<<<ROWS / 4, 512>>>(a2_w1, a2_b1, a2_w2, out);
}

// round 5
// speedup vs baseline: 1.9588x; 1.8463x over previous
#include <cuda_runtime.h>

#define BB   1024
#define AA   64
#define NN   256
#define MM   128
#define HH   64
#define EATT 64
#define ACTD 64
#define KK   8
#define ROWS (BB*AA)
#define WPAD 132   // padded weight-row stride (conflict-free LDS.128 phases)

// ---- scratch (device globals; no allocations allowed) ----
__device__ float g_thoughts[ROWS * MM];
__device__ float g_newt[ROWS * MM];
__device__ int   g_gidx[ROWS * KK];
__device__ int   g_isinit[ROWS];

// ---- packed fp32x2 FMA (Blackwell FFMA2) ----
__device__ __forceinline__ unsigned long long fma2(unsigned long long a,
                                                   unsigned long long b,
                                                   unsigned long long c)
{
    unsigned long long d;
    asm("fma.rn.f32x2 %0, %1, %2, %3;" : "=l"(d) : "l"(a), "l"(b), "l"(c));
    return d;
}
__device__ __forceinline__ float lohi(unsigned long long v)
{
    float lo = __uint_as_float((unsigned)(v & 0xffffffffull));
    float hi = __uint_as_float((unsigned)(v >> 32));
    return lo + hi;
}
__device__ __forceinline__ float sigm(float x)
{
    return 1.0f / (1.0f + __expf(-x));
}
__device__ __forceinline__ float ftanh(float x)
{
    // tanh(x) = 1 - 2/(e^{2x}+1); exact limits at +-inf, ~1e-7 rel err
    float e = __expf(2.0f * x);
    return 1.0f - __fdividef(2.0f, e + 1.0f);
}

// =====================================================================
// K12: fused actor_1 + attention.  16 rows per CTA, 512 threads.
// Thread (o = tx&127, rh = tx>>7) computes 4 rows (rh*4..rh*4+3) for the
// 128-wide layers; remapped (u = tx&63, rr = tx>>6) -> rows {rr, rr+8}
// for the 64-wide attention layers.  Weights read once per 16 rows.
// =====================================================================
__global__ __launch_bounds__(512) void k12_fused(
    const float* __restrict__ obs,
    const float* __restrict__ w1, const float* __restrict__ b1,
    const float* __restrict__ lng, const float* __restrict__ lnb,
    const float* __restrict__ w2, const float* __restrict__ b2,
    const float* __restrict__ aw1, const float* __restrict__ ab1,
    const float* __restrict__ aw2, const float* __restrict__ ab2,
    const float* __restrict__ aw3, const float* __restrict__ ab3)
{
    __shared__ __align__(16) float obs_sm[16][NN];   // 16 KB
    __shared__ __align__(16) float h_sm[16][MM];     //  8 KB
    __shared__ __align__(16) float t_sm[16][MM];     //  8 KB
    __shared__ __align__(16) float a_sm[16][EATT];   //  4 KB
    __shared__ float redA[16][4];
    __shared__ float redB[16][4];
    __shared__ float redL[16][2];

    int tx = threadIdx.x;
    int o  = tx & 127;
    int rh = tx >> 7;               // 0..3
    int wg = (tx >> 5) & 3;         // warp within rh-group
    long rowbase = (long)blockIdx.x * 16;

    // load obs tile (vectorized, coalesced)
    {
        const float4* src = (const float4*)(obs + rowbase * NN);
        float4* dst = (float4*)&obs_sm[0][0];
        #pragma unroll
        for (int i = 0; i < 2; i++) dst[tx + i * 512] = src[tx + i * 512];
    }
    __syncthreads();

    // ---- GEMM1: h[r][o] = W1[o,:] . obs[r,:] + b1[o]  (4 rows/thread) ----
    unsigned long long acc[8];      // 4 rows x 2 halves
    #pragma unroll
    for (int i = 0; i < 8; i++) acc[i] = 0ull;
    {
        const float* wr = w1 + o * NN;
        #pragma unroll 4
        for (int jc = 0; jc < NN; jc += 4) {
            longlong2 w = *(const longlong2*)(wr + jc);
            #pragma unroll
            for (int r = 0; r < 4; r++) {
                longlong2 x = *(const longlong2*)&obs_sm[rh * 4 + r][jc];
                acc[2 * r]     = fma2(w.x, x.x, acc[2 * r]);
                acc[2 * r + 1] = fma2(w.y, x.y, acc[2 * r + 1]);
            }
        }
    }
    float hv[4];
    #pragma unroll
    for (int r = 0; r < 4; r++) hv[r] = b1[o] + lohi(acc[2 * r]) + lohi(acc[2 * r + 1]);

    // ---- layernorm over o (128) per row ----
    #pragma unroll
    for (int r = 0; r < 4; r++) {
        float s = hv[r];
        for (int off = 16; off; off >>= 1) s += __shfl_down_sync(0xffffffffu, s, off);
        if ((tx & 31) == 0) redA[rh * 4 + r][wg] = s;
    }
    __syncthreads();
    float mu[4];
    #pragma unroll
    for (int r = 0; r < 4; r++) {
        int row = rh * 4 + r;
        mu[r] = (redA[row][0] + redA[row][1] + redA[row][2] + redA[row][3]) * (1.0f / MM);
    }
    #pragma unroll
    for (int r = 0; r < 4; r++) {
        float d = hv[r] - mu[r];
        float s2 = d * d;
        for (int off = 16; off; off >>= 1) s2 += __shfl_down_sync(0xffffffffu, s2, off);
        if ((tx & 31) == 0) redB[rh * 4 + r][wg] = s2;
    }
    __syncthreads();
    #pragma unroll
    for (int r = 0; r < 4; r++) {
        int row = rh * 4 + r;
        float var = (redB[row][0] + redB[row][1] + redB[row][2] + redB[row][3]) * (1.0f / MM);
        float v = (hv[r] - mu[r]) * rsqrtf(var + 1e-5f) * lng[o] + lnb[o];
        h_sm[row][o] = fmaxf(v, 0.0f);
    }
    __syncthreads();

    // ---- GEMM2: thoughts[r][o] = W2[o,:] . relu(h[r,:]) + b2[o] ----
    #pragma unroll
    for (int i = 0; i < 8; i++) acc[i] = 0ull;
    {
        const float* wr = w2 + o * MM;
        #pragma unroll 4
        for (int jc = 0; jc < MM; jc += 4) {
            longlong2 w = *(const longlong2*)(wr + jc);
            #pragma unroll
            for (int r = 0; r < 4; r++) {
                longlong2 x = *(const longlong2*)&h_sm[rh * 4 + r][jc];
                acc[2 * r]     = fma2(w.x, x.x, acc[2 * r]);
                acc[2 * r + 1] = fma2(w.y, x.y, acc[2 * r + 1]);
            }
        }
    }
    #pragma unroll
    for (int r = 0; r < 4; r++) {
        int row = rh * 4 + r;
        float t = b2[o] + lohi(acc[2 * r]) + lohi(acc[2 * r + 1]);
        t_sm[row][o] = t;
        g_thoughts[(rowbase + row) * MM + o] = t;
    }
    __syncthreads();

    // ---- attention MLP (64-wide): u = tx&63, rows {rr, rr+8} ----
    int u  = tx & 63;
    int rr = tx >> 6;               // 0..7
    unsigned long long b0a = 0ull, b0b = 0ull, b1a = 0ull, b1b = 0ull;
    {
        const float* wr = aw1 + u * MM;
        #pragma unroll 4
        for (int jc = 0; jc < MM; jc += 4) {
            longlong2 w = *(const longlong2*)(wr + jc);
            longlong2 xa = *(const longlong2*)&t_sm[rr][jc];
            longlong2 xb = *(const longlong2*)&t_sm[rr + 8][jc];
            b0a = fma2(w.x, xa.x, b0a);  b0b = fma2(w.y, xa.y, b0b);
            b1a = fma2(w.x, xb.x, b1a);  b1b = fma2(w.y, xb.y, b1b);
        }
    }
    a_sm[rr][u]     = fmaxf(ab1[u] + lohi(b0a) + lohi(b0b), 0.0f);
    a_sm[rr + 8][u] = fmaxf(ab1[u] + lohi(b1a) + lohi(b1b), 0.0f);
    __syncthreads();

    b0a = b0b = b1a = b1b = 0ull;
    {
        const float* wr = aw2 + u * EATT;
        #pragma unroll 4
        for (int jc = 0; jc < EATT; jc += 4) {
            longlong2 w = *(const longlong2*)(wr + jc);
            longlong2 xa = *(const longlong2*)&a_sm[rr][jc];
            longlong2 xb = *(const longlong2*)&a_sm[rr + 8][jc];
            b0a = fma2(w.x, xa.x, b0a);  b0b = fma2(w.y, xa.y, b0b);
            b1a = fma2(w.x, xb.x, b1a);  b1b = fma2(w.y, xb.y, b1b);
        }
    }
    float c0 = fmaxf(ab2[u] + lohi(b0a) + lohi(b0b), 0.0f);
    float c1 = fmaxf(ab2[u] + lohi(b1a) + lohi(b1b), 0.0f);

    // logit reduce over u (spans 2 warps per rr): hw = warp parity
    int hw = (tx >> 5) & 1;
    float w3u = aw3[u];
    float p0 = w3u * c0, p1 = w3u * c1;
    for (int off = 16; off; off >>= 1) {
        p0 += __shfl_down_sync(0xffffffffu, p0, off);
        p1 += __shfl_down_sync(0xffffffffu, p1, off);
    }
    if ((tx & 31) == 0) { redL[rr][hw] = p0; redL[rr + 8][hw] = p1; }
    __syncthreads();
    if (u == 0) {
        float l0 = redL[rr][0] + redL[rr][1] + ab3[0];
        float l1 = redL[rr + 8][0] + redL[rr + 8][1] + ab3[0];
        g_isinit[rowbase + rr]     = (l0 > 0.0f) ? 1 : 0;
        g_isinit[rowbase + rr + 8] = (l1 > 0.0f) ? 1 : 0;
    }
}

// =====================================================================
// K3: pairwise squared distances + stable top-8 by (dist, index),
// output indices sorted ascending.  One CTA per batch.
// =====================================================================
#define TP 132
__global__ __launch_bounds__(256) void k3_groups()
{
    __shared__ __align__(16) float th[AA][TP];
    __shared__ float sq[AA];

    int tx = threadIdx.x;
    int b  = blockIdx.x;
    const float* tg = g_thoughts + (long)b * AA * MM;
    for (int i = tx; i < AA * MM; i += 256) th[i >> 7][i & 127] = tg[i];
    __syncthreads();

    if (tx < AA) {
        float s = 0.0f;
        #pragma unroll 16
        for (int c = 0; c < MM; c++) { float v = th[tx][c]; s += v * v; }
        sq[tx] = s;
    }
    __syncthreads();

    int warp = tx >> 5, lane = tx & 31;
    for (int i = warp; i < AA; i += 8) {
        int j0 = lane, j1 = lane + 32;
        float d0 = 0.0f, d1 = 0.0f;
        #pragma unroll 8
        for (int c = 0; c < MM; c += 4) {
            float4 xi = *(const float4*)&th[i][c];
            float4 xa = *(const float4*)&th[j0][c];
            float4 xb = *(const float4*)&th[j1][c];
            d0 += xi.x * xa.x + xi.y * xa.y + xi.z * xa.z + xi.w * xa.w;
            d1 += xi.x * xb.x + xi.y * xb.y + xi.z * xb.z + xi.w * xb.w;
        }
        d0 = sq[i] + sq[j0] - 2.0f * d0;
        d1 = sq[i] + sq[j1] - 2.0f * d1;

        int sel[KK];
        #pragma unroll
        for (int t = 0; t < KK; t++) {
            float md; int mj;
            if (d0 <= d1) { md = d0; mj = j0; } else { md = d1; mj = j1; }
            for (int off = 16; off; off >>= 1) {
                float od = __shfl_down_sync(0xffffffffu, md, off);
                int   oj = __shfl_down_sync(0xffffffffu, mj, off);
                if (od < md || (od == md && oj < mj)) { md = od; mj = oj; }
            }
            mj = __shfl_sync(0xffffffffu, mj, 0);
            sel[t] = mj;
            if (mj == j0) d0 = 3.4e38f;
            if (mj == j1) d1 = 3.4e38f;
        }
        #pragma unroll
        for (int p = 0; p < KK; p++)
            #pragma unroll
            for (int q = 0; q < KK - 1; q++)
                if (sel[q] > sel[q + 1]) { int t2 = sel[q]; sel[q] = sel[q + 1]; sel[q + 1] = t2; }
        if (lane < KK) {
            int v = sel[0];                       // no dynamic reg indexing
            #pragma unroll
            for (int q = 1; q < KK; q++) if (lane == q) v = sel[q];
            g_gidx[((long)b * AA + i) * KK + lane] = v;
        }
    }
}

// =====================================================================
// K4: sequential gather -> bi-LSTM -> scatter per initiator.
// One CTA per batch, 512 threads (warps 0-7 fwd, 8-15 bwd).
// Wih_fwd in SMEM; Wih_bwd streamed (L1/L2); Whh rows in registers as
// packed f32x2.  Recurrence fully unrolled (no local-memory arrays),
// per-direction named barriers, fast transcendentals.
// =====================================================================
__global__ __launch_bounds__(512, 1) void k4_lstm(
    const float* __restrict__ wih_f, const float* __restrict__ whh_f,
    const float* __restrict__ bih_f, const float* __restrict__ bhh_f,
    const float* __restrict__ wih_b, const float* __restrict__ whh_b,
    const float* __restrict__ bih_b, const float* __restrict__ bhh_b)
{
    extern __shared__ __align__(16) float dynsm[];
    float* nt   = dynsm;            // AA*MM floats (32 KB)
    float* w_sm = dynsm + AA * MM;  // 256 x WPAD floats (135 KB): Wih_fwd

    __shared__ __align__(16) float z_sm[512];
    __shared__ __align__(16) float h_sm[2 * HH];
    __shared__ __align__(16) float hist[2][KK][HH];

    int tx  = threadIdx.x;
    int b   = blockIdx.x;
    int dir = tx >> 8;
    int g   = tx & 255;
    int barid = 1 + dir;

    float bsum = dir ? (bih_b[g] + bhh_b[g]) : (bih_f[g] + bhh_f[g]);

    // Whh row, register-resident (32 packed f32x2 = 64 regs)
    unsigned long long wr2[HH / 2];
    {
        const float* w = (dir ? whh_b : whh_f) + g * HH;
        #pragma unroll
        for (int j = 0; j < HH; j += 4) {
            longlong2 t = *(const longlong2*)(w + j);
            wr2[(j >> 1)]     = t.x;
            wr2[(j >> 1) + 1] = t.y;
        }
    }

    // stage Wih_fwd -> smem (vectorized, padded stride)
    for (int i = tx; i < 256 * (MM / 4); i += 512) {
        int r = i >> 5, c4 = i & 31;
        ((float4*)(w_sm + r * WPAD))[c4] = ((const float4*)wih_f)[i];
    }
    // load thought state (vectorized)
    {
        const float4* src = (const float4*)(g_thoughts + (long)b * AA * MM);
        float4* dst = (float4*)nt;
        #pragma unroll
        for (int i = 0; i < 4; i++) dst[tx + i * 512] = src[tx + i * 512];
    }

    const float* wrow_g = wih_b + g * MM;           // bwd weights (global)
    const float* wrow_s = w_sm + g * WPAD;          // fwd weights (smem)
    const int*   idxg   = g_gidx   + (long)b * AA * KK;
    const int*   initg  = g_isinit + (long)b * AA;
    bool is_gate = (g < HH);
    __syncthreads();

    for (int a = 0; a < AA; a++) {
        if (!initg[a]) continue;                    // block-uniform

        // per-thread gather bases (uniform loads, L1-cached line)
        int ib0 = idxg[a * KK + 0] * MM, ib1 = idxg[a * KK + 1] * MM;
        int ib2 = idxg[a * KK + 2] * MM, ib3 = idxg[a * KK + 3] * MM;
        int ib4 = idxg[a * KK + 4] * MM, ib5 = idxg[a * KK + 5] * MM;
        int ib6 = idxg[a * KK + 6] * MM, ib7 = idxg[a * KK + 7] * MM;

        // ---- input projections for all 8 timesteps ----
        unsigned long long acc[KK];
        #pragma unroll
        for (int k = 0; k < KK; k++) acc[k] = 0ull;
        if (dir == 0) {
            #pragma unroll 2
            for (int jc = 0; jc < MM; jc += 4) {
                longlong2 w = *(const longlong2*)(wrow_s + jc);
                longlong2 x0 = *(const longlong2*)(nt + ib0 + jc);
                longlong2 x1 = *(const longlong2*)(nt + ib1 + jc);
                longlong2 x2 = *(const longlong2*)(nt + ib2 + jc);
                longlong2 x3 = *(const longlong2*)(nt + ib3 + jc);
                longlong2 x4 = *(const longlong2*)(nt + ib4 + jc);
                longlong2 x5 = *(const longlong2*)(nt + ib5 + jc);
                longlong2 x6 = *(const longlong2*)(nt + ib6 + jc);
                longlong2 x7 = *(const longlong2*)(nt + ib7 + jc);
                acc[0] = fma2(w.x, x0.x, acc[0]); acc[0] = fma2(w.y, x0.y, acc[0]);
                acc[1] = fma2(w.x, x1.x, acc[1]); acc[1] = fma2(w.y, x1.y, acc[1]);
                acc[2] = fma2(w.x, x2.x, acc[2]); acc[2] = fma2(w.y, x2.y, acc[2]);
                acc[3] = fma2(w.x, x3.x, acc[3]); acc[3] = fma2(w.y, x3.y, acc[3]);
                acc[4] = fma2(w.x, x4.x, acc[4]); acc[4] = fma2(w.y, x4.y, acc[4]);
                acc[5] = fma2(w.x, x5.x, acc[5]); acc[5] = fma2(w.y, x5.y, acc[5]);
                acc[6] = fma2(w.x, x6.x, acc[6]); acc[6] = fma2(w.y, x6.y, acc[6]);
                acc[7] = fma2(w.x, x7.x, acc[7]); acc[7] = fma2(w.y, x7.y, acc[7]);
            }
        } else {
            #pragma unroll 2
            for (int jc = 0; jc < MM; jc += 4) {
                longlong2 w = *(const longlong2*)(wrow_g + jc);
                longlong2 x0 = *(const longlong2*)(nt + ib0 + jc);
                longlong2 x1 = *(const longlong2*)(nt + ib1 + jc);
                longlong2 x2 = *(const longlong2*)(nt + ib2 + jc);
                longlong2 x3 = *(const longlong2*)(nt + ib3 + jc);
                longlong2 x4 = *(const longlong2*)(nt + ib4 + jc);
                longlong2 x5 = *(const longlong2*)(nt + ib5 + jc);
                longlong2 x6 = *(const longlong2*)(nt + ib6 + jc);
                longlong2 x7 = *(const longlong2*)(nt + ib7 + jc);
                acc[0] = fma2(w.x, x0.x, acc[0]); acc[0] = fma2(w.y, x0.y, acc[0]);
                acc[1] = fma2(w.x, x1.x, acc[1]); acc[1] = fma2(w.y, x1.y, acc[1]);
                acc[2] = fma2(w.x, x2.x, acc[2]); acc[2] = fma2(w.y, x2.y, acc[2]);
                acc[3] = fma2(w.x, x3.x, acc[3]); acc[3] = fma2(w.y, x3.y, acc[3]);
                acc[4] = fma2(w.x, x4.x, acc[4]); acc[4] = fma2(w.y, x4.y, acc[4]);
                acc[5] = fma2(w.x, x5.x, acc[5]); acc[5] = fma2(w.y, x5.y, acc[5]);
                acc[6] = fma2(w.x, x6.x, acc[6]); acc[6] = fma2(w.y, x6.y, acc[6]);
                acc[7] = fma2(w.x, x7.x, acc[7]); acc[7] = fma2(w.y, x7.y, acc[7]);
            }
        }
        float xz[KK];
        #pragma unroll
        for (int k = 0; k < KK; k++) xz[k] = bsum + lohi(acc[k]);

        // ---- recurrence: fully unrolled, per-dir named barriers ----
        float cst = 0.0f;
        if (is_gate) h_sm[dir * HH + g] = 0.0f;
        asm volatile("bar.sync %0, 256;" :: "r"(barid) : "memory");

        const float* hp = &h_sm[dir * HH];
        #pragma unroll
        for (int s = 0; s < KK; s++) {
            int ks = dir ? (KK - 1 - s) : s;          // both constant per unrolled s
            unsigned long long r0 = 0ull, r1 = 0ull;
            #pragma unroll
            for (int j = 0; j < HH; j += 4) {
                longlong2 h2 = *(const longlong2*)(hp + j);
                r0 = fma2(wr2[(j >> 1)],     h2.x, r0);
                r1 = fma2(wr2[(j >> 1) + 1], h2.y, r1);
            }
            float xzk = dir ? xz[KK - 1 - s] : xz[s]; // constant indices (SEL)
            z_sm[tx] = xzk + lohi(r0) + lohi(r1);
            asm volatile("bar.sync %0, 256;" :: "r"(barid) : "memory");
            if (is_gate) {
                int base = dir * 256;
                float zi = z_sm[base + g];
                float zf = z_sm[base + 64 + g];
                float zg = z_sm[base + 128 + g];
                float zo = z_sm[base + 192 + g];
                cst = sigm(zf) * cst + sigm(zi) * ftanh(zg);
                float h = sigm(zo) * ftanh(cst);
                h_sm[dir * HH + g] = h;
                hist[dir][ks][g] = h;
            }
            asm volatile("bar.sync %0, 256;" :: "r"(barid) : "memory");
        }

        // both directions done before scatter
        __syncthreads();

        // scatter: nt[idx[k]] = [h_fwd(k) ; h_bwd(k)]
        for (int e = tx; e < KK * MM; e += 512) {
            int k = e >> 7, c = e & 127;
            float v = (c < HH) ? hist[0][k][c] : hist[1][k][c - HH];
            int base = (k == 0) ? ib0 : (k == 1) ? ib1 : (k == 2) ? ib2 : (k == 3) ? ib3
                     : (k == 4) ? ib4 : (k == 5) ? ib5 : (k == 6) ? ib6 : ib7;
            nt[base + c] = v;
        }
        __syncthreads();
    }

    {
        float4* dst = (float4*)(g_newt + (long)b * AA * MM);
        const float4* src = (const float4*)nt;
        #pragma unroll
        for (int i = 0; i < 4; i++) dst[tx + i * 512] = src[tx + i * 512];
    }
}

// =====================================================================
// K5: actor_2.  16 rows per CTA, 512 threads, 4 rows/thread (GEMM1),
// remap (u, rr) -> rows {rr, rr+8} for the 64-wide output layer.
// =====================================================================
__global__ __launch_bounds__(512) void k5_actor2(
    const float* __restrict__ w1, const float* __restrict__ b1,
    const float* __restrict__ w2, float* __restrict__ out)
{
    __shared__ __align__(16) float x_sm[16][2 * MM];  // 16 KB
    __shared__ __align__(16) float e_sm[16][MM];      //  8 KB

    int tx = threadIdx.x;
    int o  = tx & 127;
    int rh = tx >> 7;
    long rowbase = (long)blockIdx.x * 16;

    // stage relu(concat(thoughts, newt)) vectorized
    for (int i = tx; i < 16 * 32; i += 512) {
        int r = i >> 5, c4 = i & 31;
        float4 t = ((const float4*)(g_thoughts + (rowbase + r) * MM))[c4];
        float4 n = ((const float4*)(g_newt     + (rowbase + r) * MM))[c4];
        t.x = fmaxf(t.x, 0.f); t.y = fmaxf(t.y, 0.f); t.z = fmaxf(t.z, 0.f); t.w = fmaxf(t.w, 0.f);
        n.x = fmaxf(n.x, 0.f); n.y = fmaxf(n.y, 0.f); n.z = fmaxf(n.z, 0.f); n.w = fmaxf(n.w, 0.f);
        ((float4*)&x_sm[r][0])[c4]      = t;
        ((float4*)&x_sm[r][MM])[c4]     = n;
    }
    __syncthreads();

    unsigned long long acc[8];
    #pragma unroll
    for (int i = 0; i < 8; i++) acc[i] = 0ull;
    {
        const float* wr = w1 + o * 2 * MM;
        #pragma unroll 4
        for (int jc = 0; jc < 2 * MM; jc += 4) {
            longlong2 w = *(const longlong2*)(wr + jc);
            #pragma unroll
            for (int r = 0; r < 4; r++) {
                longlong2 x = *(const longlong2*)&x_sm[rh * 4 + r][jc];
                acc[2 * r]     = fma2(w.x, x.x, acc[2 * r]);
                acc[2 * r + 1] = fma2(w.y, x.y, acc[2 * r + 1]);
            }
        }
    }
    #pragma unroll
    for (int r = 0; r < 4; r++)
        e_sm[rh * 4 + r][o] = b1[o] + lohi(acc[2 * r]) + lohi(acc[2 * r + 1]);
    __syncthreads();

    int u  = tx & 63;
    int rr = tx >> 6;
    unsigned long long c0a = 0ull, c0b = 0ull, c1a = 0ull, c1b = 0ull;
    {
        const float* wr = w2 + u * MM;
        #pragma unroll 4
        for (int jc = 0; jc < MM; jc += 4) {
            longlong2 w = *(const longlong2*)(wr + jc);
            longlong2 xa = *(const longlong2*)&e_sm[rr][jc];
            longlong2 xb = *(const longlong2*)&e_sm[rr + 8][jc];
            c0a = fma2(w.x, xa.x, c0a);  c0b = fma2(w.y, xa.y, c0b);
            c1a = fma2(w.x, xb.x, c1a);  c1b = fma2(w.y, xb.y, c1b);
        }
    }
    out[(rowbase + rr) * ACTD + u]     = ftanh(lohi(c0a) + lohi(c0b));
    out[(rowbase + rr + 8) * ACTD + u] = ftanh(lohi(c1a) + lohi(c1b));
}

// =====================================================================
extern "C" void kernel_launch(void* const* d_in, const int* in_sizes, int n_in,
                              void* d_out, int out_size)
{
    const float* obs    = (const float*)d_in[0];
    const float* a1_w1  = (const float*)d_in[1];
    const float* a1_b1  = (const float*)d_in[2];
    const float* ln_g   = (const float*)d_in[3];
    const float* ln_b   = (const float*)d_in[4];
    const float* a1_w2  = (const float*)d_in[5];
    const float* a1_b2  = (const float*)d_in[6];
    const float* att_w1 = (const float*)d_in[7];
    const float* att_b1 = (const float*)d_in[8];
    const float* att_w2 = (const float*)d_in[9];
    const float* att_b2 = (const float*)d_in[10];
    const float* att_w3 = (const float*)d_in[11];
    const float* att_b3 = (const float*)d_in[12];
    const float* wih_f  = (const float*)d_in[13];
    const float* whh_f  = (const float*)d_in[14];
    const float* bih_f  = (const float*)d_in[15];
    const float* bhh_f  = (const float*)d_in[16];
    const float* wih_b  = (const float*)d_in[17];
    const float* whh_b  = (const float*)d_in[18];
    const float* bih_b  = (const float*)d_in[19];
    const float* bhh_b  = (const float*)d_in[20];
    const float* a2_w1  = (const float*)d_in[21];
    const float* a2_b1  = (const float*)d_in[22];
    const float* a2_w2  = (const float*)d_in[23];
    float* out = (float*)d_out;

    const int k4_smem = (AA * MM + 256 * WPAD) * (int)sizeof(float);
    static int attr_done = 0;
    if (!attr_done) {
        cudaFuncSetAttribute(k4_lstm, cudaFuncAttributeMaxDynamicSharedMemorySize, k4_smem);
        attr_done = 1;
    }

    k12_fused<<<ROWS / 16, 512>>>(obs, a1_w1, a1_b1, ln_g, ln_b, a1_w2, a1_b2,
                                  att_w1, att_b1, att_w2, att_b2, att_w3, att_b3);
    k3_groups<<<BB, 256>>>();
    k4_lstm<<<BB, 512, k4_smem>>>(wih_f, whh_f, bih_f, bhh_f, wih_b, whh_b, bih_b, bhh_b);
    k5_actor2<<<ROWS / 16, 512>>>(a2_w1, a2_b1, a2_w2, out);
}